// round 14
// baseline (speedup 1.0000x reference)
#include <cuda_runtime.h>
#include <stdint.h>
#include <math.h>

// =============================== constants ===============================
namespace {
constexpr int Bz = 8, S = 2048, Dh = 128;
constexpr int CH = 16, CR = S / CH;       // 16 split-K chunks of 128 rows
constexpr int PITCHB = 272;               // smem row pitch bytes (136 bf16)
constexpr int TILE = 128 * PITCHB;        // 34816 B per 128x128 bf16 image
constexpr int SMEM_SZ = 4 * TILE;         // 139264 B (4 images, no staging)
constexpr int NT = 512;                   // threads per GEMM CTA (16 warps)
}

// =============================== scratch =================================
__device__ float    g_Mp[Bz * CH * 128 * 128];  // split-K fp32 partials (8 MB)
__device__ uint32_t g_Mh[Bz][8192];             // M hi, bf16x2 row-major [d][v]
__device__ uint32_t g_Ml[Bz][8192];             // M lo

// =============================== helpers =================================
__device__ __forceinline__ uint32_t smem_u32(const void* p) {
    uint32_t a;
    asm("{ .reg .u64 t; cvta.to.shared.u64 t, %1; cvt.u32.u64 %0, t; }"
        : "=r"(a) : "l"(p));
    return a;
}
__device__ __forceinline__ void cp16(uint32_t dst, const void* src) {
    asm volatile("cp.async.cg.shared.global [%0], [%1], 16;"
                 :: "r"(dst), "l"(src));
}
__device__ __forceinline__ void cp_commit() {
    asm volatile("cp.async.commit_group;");
}
template <int N>
__device__ __forceinline__ void cp_wait() {
    asm volatile("cp.async.wait_group %0;" :: "n"(N));
}
// pack: low half = lo operand, high half = hi operand
__device__ __forceinline__ uint32_t cvt2(float hi, float lo) {
    uint32_t r;
    asm("cvt.rn.bf16x2.f32 %0, %1, %2;" : "=r"(r) : "f"(hi), "f"(lo));
    return r;
}
__device__ __forceinline__ void ldsm4(uint32_t* r, uint32_t a) {
    asm volatile("ldmatrix.sync.aligned.m8n8.x4.shared.b16 {%0,%1,%2,%3}, [%4];"
        : "=r"(r[0]), "=r"(r[1]), "=r"(r[2]), "=r"(r[3]) : "r"(a));
}
__device__ __forceinline__ void ldsm4t(uint32_t* r, uint32_t a) {
    asm volatile("ldmatrix.sync.aligned.m8n8.x4.trans.shared.b16 {%0,%1,%2,%3}, [%4];"
        : "=r"(r[0]), "=r"(r[1]), "=r"(r[2]), "=r"(r[3]) : "r"(a));
}
__device__ __forceinline__ void mma_bf16(float* d, const uint32_t* a,
                                         const uint32_t* b) {
    asm volatile(
        "mma.sync.aligned.m16n8k16.row.col.f32.bf16.bf16.f32 "
        "{%0,%1,%2,%3}, {%4,%5,%6,%7}, {%8,%9}, {%0,%1,%2,%3};"
        : "+f"(d[0]), "+f"(d[1]), "+f"(d[2]), "+f"(d[3])
        : "r"(a[0]), "r"(a[1]), "r"(a[2]), "r"(a[3]), "r"(b[0]), "r"(b[1]));
}

// convert one float4 -> hi/lo bf16x2 pairs, store at (row, col4) in images
__device__ __forceinline__ void cvt_store(float4 x, char* hi, char* lo,
                                          int row, int c4) {
    uint32_t h0 = cvt2(x.y, x.x), h1 = cvt2(x.w, x.z);
    float a0 = __uint_as_float(h0 << 16);
    float a1 = __uint_as_float(h0 & 0xFFFF0000u);
    float a2 = __uint_as_float(h1 << 16);
    float a3 = __uint_as_float(h1 & 0xFFFF0000u);
    uint32_t l0 = cvt2(x.y - a1, x.x - a0);
    uint32_t l1 = cvt2(x.w - a3, x.z - a2);
    *(uint2*)(hi + row * PITCHB + c4 * 2) = make_uint2(h0, h1);
    *(uint2*)(lo + row * PITCHB + c4 * 2) = make_uint2(l0, l1);
}

// one k16 MMA step (ks) on the resident images; warp tile 32x32.
// ATRANS: A stored [k][m] (ldmatrix.trans); else A stored [m][k].
template <bool ATRANS>
__device__ __forceinline__ void mma_step(uint32_t aA, uint32_t bA, int ks,
                                         float acc[2][4][4]) {
    uint32_t ah[2][4], al[2][4];
    if (ATRANS) {
        const uint32_t kb = (uint32_t)(ks * 16 * PITCHB);
        ldsm4t(ah[0], aA + kb);
        ldsm4t(ah[1], aA + kb + 32);
        ldsm4t(al[0], aA + kb + TILE);
        ldsm4t(al[1], aA + kb + TILE + 32);
    } else {
        const uint32_t kb = (uint32_t)(ks * 32);
        ldsm4(ah[0], aA + kb);
        ldsm4(ah[1], aA + kb + 16 * PITCHB);
        ldsm4(al[0], aA + kb + TILE);
        ldsm4(al[1], aA + kb + TILE + 16 * PITCHB);
    }
    const uint32_t kbB = (uint32_t)(ks * 16 * PITCHB);
    uint32_t bh[8], bl[8];
    ldsm4t(&bh[0], bA + kbB);
    ldsm4t(&bh[4], bA + kbB + 32);
    ldsm4t(&bl[0], bA + kbB + TILE);
    ldsm4t(&bl[4], bA + kbB + TILE + 32);
#pragma unroll
    for (int mt = 0; mt < 2; ++mt)
#pragma unroll
        for (int j = 0; j < 4; ++j) {
            float* d = acc[mt][j];
            mma_bf16(d, ah[mt], &bh[2 * j]);
            mma_bf16(d, al[mt], &bh[2 * j]);
            mma_bf16(d, ah[mt], &bl[2 * j]);
        }
}

// fragment base addresses (warp tile 32x32, 16 warps)
template <bool ATRANS>
__device__ __forceinline__ void frag_bases(uint32_t sb, int lane, int wid,
                                           uint32_t& aA, uint32_t& bA) {
    const int m_base = (wid & 3) * 32, n_base = (wid >> 2) * 32;
    if (ATRANS) {
        aA = sb + (uint32_t)((((lane & 7) + ((lane >> 4) << 3)) * PITCHB) +
                             (m_base + ((lane >> 3) & 1) * 8) * 2);
    } else {
        aA = sb + (uint32_t)(((m_base + (lane & 7) + (((lane >> 3) & 1) << 3)) *
                              PITCHB) + ((lane >> 4) << 3) * 2);
    }
    bA = sb + 2 * TILE +
         (uint32_t)((((lane & 7) + (((lane >> 3) & 1) << 3)) * PITCHB) +
                    (n_base + ((lane >> 4) << 3)) * 2);
}

// ===== kernel 1: split-K partial of M = K^T V (2-phase reg pipeline) =====
__global__ void __launch_bounds__(NT, 1)
ktv_kernel(const float* __restrict__ Kp, const float* __restrict__ Vp) {
    extern __shared__ char sm[];
    const uint32_t sb = smem_u32(sm);
    const int tid = threadIdx.x, lane = tid & 31, wid = tid >> 5;
    const int b = blockIdx.x >> 4, c = blockIdx.x & 15;

    const float4* Kb = (const float4*)(Kp + (size_t)(b * S + c * CR) * Dh);
    const float4* Vb = (const float4*)(Vp + (size_t)(b * S + c * CR) * Dh);
    const int r = tid >> 5, ch = tid & 31;   // slab-local row, float4 col

    // batch 1: LDG slabs 0-3 into registers (64 KB/CTA in flight)
    float4 kreg[4], vreg[4];
#pragma unroll
    for (int s = 0; s < 4; ++s) {
        kreg[s] = Kb[(s * 16 + r) * 32 + ch];
        vreg[s] = Vb[(s * 16 + r) * 32 + ch];
    }
#pragma unroll
    for (int s = 0; s < 4; ++s) {
        cvt_store(kreg[s], sm, sm + TILE, s * 16 + r, ch * 4);
        cvt_store(vreg[s], sm + 2 * TILE, sm + 3 * TILE, s * 16 + r, ch * 4);
    }
    // batch 2: issue LDGs for slabs 4-7 (latency hidden under MMA 0-3)
#pragma unroll
    for (int s = 0; s < 4; ++s) {
        kreg[s] = Kb[((s + 4) * 16 + r) * 32 + ch];
        vreg[s] = Vb[((s + 4) * 16 + r) * 32 + ch];
    }
    __syncthreads();   // publish slabs 0-3 images

    uint32_t aA, bA;
    frag_bases<true>(sb, lane, wid, aA, bA);
    float acc[2][4][4] = {};

    // MMA on slabs 0-3; convert slab 4+s after step s (disjoint image rows)
#pragma unroll
    for (int s = 0; s < 4; ++s) {
        mma_step<true>(aA, bA, s, acc);
        cvt_store(kreg[s], sm, sm + TILE, (s + 4) * 16 + r, ch * 4);
        cvt_store(vreg[s], sm + 2 * TILE, sm + 3 * TILE, (s + 4) * 16 + r,
                  ch * 4);
    }
    __syncthreads();   // publish slabs 4-7 images

#pragma unroll
    for (int s = 4; s < 8; ++s) mma_step<true>(aA, bA, s, acc);

    const int m_base = (wid & 3) * 32, n_base = (wid >> 2) * 32;
    const int g = lane >> 2, t = lane & 3;
    float* outp = g_Mp + ((size_t)(b * CH + c)) * 16384;
#pragma unroll
    for (int mt = 0; mt < 2; ++mt)
#pragma unroll
        for (int nt = 0; nt < 4; ++nt) {
            const int row = m_base + mt * 16 + g, col = n_base + nt * 8 + 2 * t;
            *(float2*)&outp[row * 128 + col] =
                make_float2(acc[mt][nt][0], acc[mt][nt][1]);
            *(float2*)&outp[(row + 8) * 128 + col] =
                make_float2(acc[mt][nt][2], acc[mt][nt][3]);
        }
}

// ====== kernel 2: reduce 16 partials -> M, convert to bf16 hi/lo ======
__global__ void __launch_bounds__(256, 1) reduce_kernel() {
    const int b = blockIdx.x >> 4, seg = blockIdx.x & 15;
    const int tid = threadIdx.x;
    const int d = seg * 8 + (tid >> 5), v0 = (tid & 31) * 4;
    const float* base = g_Mp + (size_t)b * CH * 16384 + d * 128 + v0;
    float4 s = make_float4(0.f, 0.f, 0.f, 0.f);
#pragma unroll
    for (int c = 0; c < CH; ++c) {
        float4 p = *(const float4*)(base + (size_t)c * 16384);
        s.x += p.x; s.y += p.y; s.z += p.z; s.w += p.w;
    }
    uint32_t h0 = cvt2(s.y, s.x), h1 = cvt2(s.w, s.z);
    float a0 = __uint_as_float(h0 << 16), a1 = __uint_as_float(h0 & 0xFFFF0000u);
    float a2 = __uint_as_float(h1 << 16), a3 = __uint_as_float(h1 & 0xFFFF0000u);
    uint32_t l0 = cvt2(s.y - a1, s.x - a0), l1 = cvt2(s.w - a3, s.z - a2);
    const int w = d * 64 + v0 / 2;   // 64 words per 128-bf16 row
    *(uint2*)&g_Mh[b][w] = make_uint2(h0, h1);
    *(uint2*)&g_Ml[b][w] = make_uint2(l0, l1);
}

// ===== kernel 3: O tile = Q tile @ M (scaled); 1 barrier, 8 MMA steps =====
__global__ void __launch_bounds__(NT, 1)
qm_kernel(const float* __restrict__ Qp, const float* __restrict__ sfp,
          float* __restrict__ Op) {
    extern __shared__ char sm[];
    const uint32_t sb = smem_u32(sm);
    const int tid = threadIdx.x, lane = tid & 31, wid = tid >> 5;
    const int b = blockIdx.x >> 4, qt = blockIdx.x & 15;

    // M hi/lo -> pitched images via cp.async (one group; L2-resident source)
    {
        const int hsel = tid >> 8;           // 0: hi image, 1: lo image
        const int it = tid & 255;
        const int mrow = it >> 1;            // 0..127
        const int mcb = (it & 1) * 8;        // 16B-chunk base: 0 or 8
        const char* msrc =
            (hsel ? (const char*)g_Ml[b] : (const char*)g_Mh[b]) +
            (size_t)mrow * 256 + mcb * 16;
        const uint32_t mdst =
            sb + (hsel ? 3 : 2) * TILE + mrow * PITCHB + mcb * 16;
#pragma unroll
        for (int i = 0; i < 8; ++i) cp16(mdst + i * 16, msrc + i * 16);
        cp_commit();
    }
    // Q tile -> registers (64 KB/CTA in flight), then convert
    const int qr = tid >> 2, qc = tid & 3;
    {
        const float4* Qb =
            (const float4*)(Qp + (size_t)(b * S + qt * 128) * Dh);
        float4 qreg[8];
#pragma unroll
        for (int s = 0; s < 8; ++s) qreg[s] = Qb[qr * 32 + s * 4 + qc];
#pragma unroll
        for (int s = 0; s < 8; ++s)
            cvt_store(qreg[s], sm, sm + TILE, qr, s * 16 + qc * 4);
    }
    cp_wait<0>();
    __syncthreads();   // publish all images

    uint32_t aA, bA;
    frag_bases<false>(sb, lane, wid, aA, bA);
    float acc[2][4][4] = {};

#pragma unroll
    for (int s = 0; s < 8; ++s) mma_step<false>(aA, bA, s, acc);

    const float inv = 1.0f / (sqrtf(128.0f) * sfp[0]);
    const int m_base = (wid & 3) * 32, n_base = (wid >> 2) * 32;
    const int g = lane >> 2, t = lane & 3;
    float* outp = Op + (size_t)(b * S + qt * 128) * 128;
#pragma unroll
    for (int mt = 0; mt < 2; ++mt)
#pragma unroll
        for (int nt = 0; nt < 4; ++nt) {
            const int row = m_base + mt * 16 + g, col = n_base + nt * 8 + 2 * t;
            *(float2*)&outp[row * 128 + col] =
                make_float2(acc[mt][nt][0] * inv, acc[mt][nt][1] * inv);
            *(float2*)&outp[(row + 8) * 128 + col] =
                make_float2(acc[mt][nt][2] * inv, acc[mt][nt][3] * inv);
        }
}

// =============================== launch ===============================
extern "C" void kernel_launch(void* const* d_in, const int* in_sizes, int n_in,
                              void* d_out, int out_size) {
    // metadata order: qk (unused), qk_scaling_factor, query, key, value
    const float* sf = (const float*)d_in[1];
    const float* Q  = (const float*)d_in[2];
    const float* K  = (const float*)d_in[3];
    const float* V  = (const float*)d_in[4];
    float* O        = (float*)d_out;

    cudaFuncSetAttribute(ktv_kernel,
                         cudaFuncAttributeMaxDynamicSharedMemorySize, SMEM_SZ);
    cudaFuncSetAttribute(qm_kernel,
                         cudaFuncAttributeMaxDynamicSharedMemorySize, SMEM_SZ);

    ktv_kernel<<<Bz * CH, NT, SMEM_SZ>>>(K, V);
    reduce_kernel<<<Bz * CH, 256>>>();
    qm_kernel<<<Bz * CH, NT, SMEM_SZ>>>(Q, sf, O);
}

// round 15
// speedup vs baseline: 1.0111x; 1.0111x over previous
#include <cuda_runtime.h>
#include <stdint.h>
#include <math.h>

// =============================== constants ===============================
namespace {
constexpr int Bz = 8, S = 2048, Dh = 128;
constexpr int CH = 16, CR = S / CH;       // 16 split-K chunks of 128 rows
constexpr int PITCHB = 272;               // smem row pitch bytes (136 bf16)
constexpr int TILE = 128 * PITCHB;        // 34816 B per 128x128 bf16 image
constexpr int SMEM_SZ = 4 * TILE;         // 139264 B (4 images)
constexpr int NT = 512;                   // threads per CTA (16 warps)
}

// =============================== scratch =================================
__device__ float    g_Mp[Bz * CH * 128 * 128];  // split-K fp32 partials (8 MB)
__device__ uint32_t g_Mh[Bz][8192];             // M hi, bf16x2 row-major [d][v]
__device__ uint32_t g_Ml[Bz][8192];             // M lo
__device__ unsigned g_c1[Bz];                   // zero-init; self-resetting
__device__ unsigned g_c2[Bz];
__device__ unsigned g_c3[Bz];

// =============================== helpers =================================
__device__ __forceinline__ uint32_t smem_u32(const void* p) {
    uint32_t a;
    asm("{ .reg .u64 t; cvta.to.shared.u64 t, %1; cvt.u32.u64 %0, t; }"
        : "=r"(a) : "l"(p));
    return a;
}
__device__ __forceinline__ void cp16(uint32_t dst, const void* src) {
    asm volatile("cp.async.cg.shared.global [%0], [%1], 16;"
                 :: "r"(dst), "l"(src));
}
__device__ __forceinline__ void cp_commit() {
    asm volatile("cp.async.commit_group;");
}
template <int N>
__device__ __forceinline__ void cp_wait() {
    asm volatile("cp.async.wait_group %0;" :: "n"(N));
}
// pack: low half = lo operand, high half = hi operand
__device__ __forceinline__ uint32_t cvt2(float hi, float lo) {
    uint32_t r;
    asm("cvt.rn.bf16x2.f32 %0, %1, %2;" : "=r"(r) : "f"(hi), "f"(lo));
    return r;
}
__device__ __forceinline__ void ldsm4(uint32_t* r, uint32_t a) {
    asm volatile("ldmatrix.sync.aligned.m8n8.x4.shared.b16 {%0,%1,%2,%3}, [%4];"
        : "=r"(r[0]), "=r"(r[1]), "=r"(r[2]), "=r"(r[3]) : "r"(a));
}
__device__ __forceinline__ void ldsm4t(uint32_t* r, uint32_t a) {
    asm volatile("ldmatrix.sync.aligned.m8n8.x4.trans.shared.b16 {%0,%1,%2,%3}, [%4];"
        : "=r"(r[0]), "=r"(r[1]), "=r"(r[2]), "=r"(r[3]) : "r"(a));
}
__device__ __forceinline__ void mma_bf16(float* d, const uint32_t* a,
                                         const uint32_t* b) {
    asm volatile(
        "mma.sync.aligned.m16n8k16.row.col.f32.bf16.bf16.f32 "
        "{%0,%1,%2,%3}, {%4,%5,%6,%7}, {%8,%9}, {%0,%1,%2,%3};"
        : "+f"(d[0]), "+f"(d[1]), "+f"(d[2]), "+f"(d[3])
        : "r"(a[0]), "r"(a[1]), "r"(a[2]), "r"(a[3]), "r"(b[0]), "r"(b[1]));
}

// convert one float4 -> hi/lo bf16x2 pairs, store at (row, col4) in images
__device__ __forceinline__ void cvt_store(float4 x, char* hi, char* lo,
                                          int row, int c4) {
    uint32_t h0 = cvt2(x.y, x.x), h1 = cvt2(x.w, x.z);
    float a0 = __uint_as_float(h0 << 16);
    float a1 = __uint_as_float(h0 & 0xFFFF0000u);
    float a2 = __uint_as_float(h1 << 16);
    float a3 = __uint_as_float(h1 & 0xFFFF0000u);
    uint32_t l0 = cvt2(x.y - a1, x.x - a0);
    uint32_t l1 = cvt2(x.w - a3, x.z - a2);
    *(uint2*)(hi + row * PITCHB + c4 * 2) = make_uint2(h0, h1);
    *(uint2*)(lo + row * PITCHB + c4 * 2) = make_uint2(l0, l1);
}

// one k16 MMA step (ks) on the resident images; warp tile 32x32.
// ATRANS: A stored [k][m] (ldmatrix.trans); else A stored [m][k].
template <bool ATRANS>
__device__ __forceinline__ void mma_step(uint32_t aA, uint32_t bA, int ks,
                                         float acc[2][4][4]) {
    uint32_t ah[2][4], al[2][4];
    if (ATRANS) {
        const uint32_t kb = (uint32_t)(ks * 16 * PITCHB);
        ldsm4t(ah[0], aA + kb);
        ldsm4t(ah[1], aA + kb + 32);
        ldsm4t(al[0], aA + kb + TILE);
        ldsm4t(al[1], aA + kb + TILE + 32);
    } else {
        const uint32_t kb = (uint32_t)(ks * 32);
        ldsm4(ah[0], aA + kb);
        ldsm4(ah[1], aA + kb + 16 * PITCHB);
        ldsm4(al[0], aA + kb + TILE);
        ldsm4(al[1], aA + kb + TILE + 16 * PITCHB);
    }
    const uint32_t kbB = (uint32_t)(ks * 16 * PITCHB);
    uint32_t bh[8], bl[8];
    ldsm4t(&bh[0], bA + kbB);
    ldsm4t(&bh[4], bA + kbB + 32);
    ldsm4t(&bl[0], bA + kbB + TILE);
    ldsm4t(&bl[4], bA + kbB + TILE + 32);
#pragma unroll
    for (int mt = 0; mt < 2; ++mt)
#pragma unroll
        for (int j = 0; j < 4; ++j) {
            float* d = acc[mt][j];
            mma_bf16(d, ah[mt], &bh[2 * j]);
            mma_bf16(d, al[mt], &bh[2 * j]);
            mma_bf16(d, ah[mt], &bl[2 * j]);
        }
}

// fragment base addresses (warp tile 32x32, 16 warps)
template <bool ATRANS>
__device__ __forceinline__ void frag_bases(uint32_t sb, int lane, int wid,
                                           uint32_t& aA, uint32_t& bA) {
    const int m_base = (wid & 3) * 32, n_base = (wid >> 2) * 32;
    if (ATRANS) {
        aA = sb + (uint32_t)((((lane & 7) + ((lane >> 4) << 3)) * PITCHB) +
                             (m_base + ((lane >> 3) & 1) * 8) * 2);
    } else {
        aA = sb + (uint32_t)(((m_base + (lane & 7) + (((lane >> 3) & 1) << 3)) *
                              PITCHB) + ((lane >> 4) << 3) * 2);
    }
    bA = sb + 2 * TILE +
         (uint32_t)((((lane & 7) + (((lane >> 3) & 1) << 3)) * PITCHB) +
                    (n_base + ((lane >> 4) << 3)) * 2);
}

// spin until counter[b] >= 16 (tid 0 only), then block-wide acquire
__device__ __forceinline__ void batch_wait(unsigned* ctr, int tid) {
    __threadfence();                    // release prior writes
    if (tid == 0) {
        atomicAdd(ctr, 1u);
        volatile unsigned* f = ctr;
        while (*f < CH) { __nanosleep(64); }
    }
    __syncthreads();
    __threadfence();                    // acquire others' writes
}

// ======================= fused kernel (one launch) =======================
__global__ void __launch_bounds__(NT, 1)
fused_kernel(const float* __restrict__ Qp, const float* __restrict__ Kp,
             const float* __restrict__ Vp, const float* __restrict__ sfp,
             float* __restrict__ Op) {
    extern __shared__ char sm[];
    const uint32_t sb = smem_u32(sm);
    const int tid = threadIdx.x, lane = tid & 31, wid = tid >> 5;
    const int b = blockIdx.x >> 4, c = blockIdx.x & 15;

    // ---------------- phase 1: split-K partial of M = K^T V ----------------
    {
        const float4* Kb = (const float4*)(Kp + (size_t)(b * S + c * CR) * Dh);
        const float4* Vb = (const float4*)(Vp + (size_t)(b * S + c * CR) * Dh);
        const int r = tid >> 5, ch = tid & 31;

        float4 kreg[4], vreg[4];
#pragma unroll
        for (int s = 0; s < 4; ++s) {
            kreg[s] = Kb[(s * 16 + r) * 32 + ch];
            vreg[s] = Vb[(s * 16 + r) * 32 + ch];
        }
#pragma unroll
        for (int s = 0; s < 4; ++s) {
            cvt_store(kreg[s], sm, sm + TILE, s * 16 + r, ch * 4);
            cvt_store(vreg[s], sm + 2 * TILE, sm + 3 * TILE, s * 16 + r,
                      ch * 4);
        }
#pragma unroll
        for (int s = 0; s < 4; ++s) {
            kreg[s] = Kb[((s + 4) * 16 + r) * 32 + ch];
            vreg[s] = Vb[((s + 4) * 16 + r) * 32 + ch];
        }
        __syncthreads();

        uint32_t aA, bA;
        frag_bases<true>(sb, lane, wid, aA, bA);
        float acc[2][4][4] = {};

#pragma unroll
        for (int s = 0; s < 4; ++s) {
            mma_step<true>(aA, bA, s, acc);
            cvt_store(kreg[s], sm, sm + TILE, (s + 4) * 16 + r, ch * 4);
            cvt_store(vreg[s], sm + 2 * TILE, sm + 3 * TILE, (s + 4) * 16 + r,
                      ch * 4);
        }
        __syncthreads();
#pragma unroll
        for (int s = 4; s < 8; ++s) mma_step<true>(aA, bA, s, acc);

        const int m_base = (wid & 3) * 32, n_base = (wid >> 2) * 32;
        const int g = lane >> 2, t = lane & 3;
        float* outp = g_Mp + ((size_t)(b * CH + c)) * 16384;
#pragma unroll
        for (int mt = 0; mt < 2; ++mt)
#pragma unroll
            for (int nt = 0; nt < 4; ++nt) {
                const int row = m_base + mt * 16 + g;
                const int col = n_base + nt * 8 + 2 * t;
                *(float2*)&outp[row * 128 + col] =
                    make_float2(acc[mt][nt][0], acc[mt][nt][1]);
                *(float2*)&outp[(row + 8) * 128 + col] =
                    make_float2(acc[mt][nt][2], acc[mt][nt][3]);
            }
    }

    batch_wait(&g_c1[b], tid);   // all 16 partials of batch b visible

    // ------- phase 2: reduce this CTA's 8 M-rows, write bf16 images -------
    {
        const int lr = tid >> 6;             // 0..7
        const int d  = c * 8 + lr;           // M row this thread helps reduce
        const int v0 = (tid & 63) * 2;       // column pair
        const float* base = g_Mp + (size_t)b * CH * 16384 + d * 128 + v0;
        float2 s2 = make_float2(0.f, 0.f);
#pragma unroll
        for (int cc = 0; cc < CH; ++cc) {
            float2 p = *(const float2*)(base + (size_t)cc * 16384);
            s2.x += p.x; s2.y += p.y;
        }
        uint32_t h = cvt2(s2.y, s2.x);
        float a0 = __uint_as_float(h << 16);
        float a1 = __uint_as_float(h & 0xFFFF0000u);
        uint32_t l = cvt2(s2.y - a1, s2.x - a0);
        const int w = d * 64 + v0 / 2;
        g_Mh[b][w] = h;
        g_Ml[b][w] = l;
    }

    batch_wait(&g_c2[b], tid);   // full M image of batch b visible

    // counters self-reset (all 16 CTAs passed both waits already)
    if (tid == 0) {
        unsigned v = atomicAdd(&g_c3[b], 1u);
        if (v == CH - 1) {
            *(volatile unsigned*)&g_c1[b] = 0u;
            *(volatile unsigned*)&g_c2[b] = 0u;
            *(volatile unsigned*)&g_c3[b] = 0u;
        }
    }

    // ---------------- phase 3: O tile = Q tile @ M (scaled) ----------------
    {
        // M hi/lo -> pitched images via cp.async (one group)
        {
            const int hsel = tid >> 8;
            const int it = tid & 255;
            const int mrow = it >> 1;
            const int mcb = (it & 1) * 8;
            const char* msrc =
                (hsel ? (const char*)g_Ml[b] : (const char*)g_Mh[b]) +
                (size_t)mrow * 256 + mcb * 16;
            const uint32_t mdst =
                sb + (hsel ? 3 : 2) * TILE + mrow * PITCHB + mcb * 16;
#pragma unroll
            for (int i = 0; i < 8; ++i) cp16(mdst + i * 16, msrc + i * 16);
            cp_commit();
        }
        const int qr = tid >> 2, qc = tid & 3;
        {
            const float4* Qb =
                (const float4*)(Qp + (size_t)(b * S + c * 128) * Dh);
            float4 qreg[8];
#pragma unroll
            for (int s = 0; s < 8; ++s) qreg[s] = Qb[qr * 32 + s * 4 + qc];
#pragma unroll
            for (int s = 0; s < 8; ++s)
                cvt_store(qreg[s], sm, sm + TILE, qr, s * 16 + qc * 4);
        }
        cp_wait<0>();
        __syncthreads();

        uint32_t aA, bA;
        frag_bases<false>(sb, lane, wid, aA, bA);
        float acc[2][4][4] = {};
#pragma unroll
        for (int s = 0; s < 8; ++s) mma_step<false>(aA, bA, s, acc);

        const float inv = 1.0f / (sqrtf(128.0f) * sfp[0]);
        const int m_base = (wid & 3) * 32, n_base = (wid >> 2) * 32;
        const int g = lane >> 2, t = lane & 3;
        float* outp = Op + (size_t)(b * S + c * 128) * 128;
#pragma unroll
        for (int mt = 0; mt < 2; ++mt)
#pragma unroll
            for (int nt = 0; nt < 4; ++nt) {
                const int row = m_base + mt * 16 + g;
                const int col = n_base + nt * 8 + 2 * t;
                *(float2*)&outp[row * 128 + col] =
                    make_float2(acc[mt][nt][0] * inv, acc[mt][nt][1] * inv);
                *(float2*)&outp[(row + 8) * 128 + col] =
                    make_float2(acc[mt][nt][2] * inv, acc[mt][nt][3] * inv);
            }
    }
}

// =============================== launch ===============================
extern "C" void kernel_launch(void* const* d_in, const int* in_sizes, int n_in,
                              void* d_out, int out_size) {
    // metadata order: qk (unused), qk_scaling_factor, query, key, value
    const float* sf = (const float*)d_in[1];
    const float* Q  = (const float*)d_in[2];
    const float* K  = (const float*)d_in[3];
    const float* V  = (const float*)d_in[4];
    float* O        = (float*)d_out;

    cudaFuncSetAttribute(fused_kernel,
                         cudaFuncAttributeMaxDynamicSharedMemorySize, SMEM_SZ);
    fused_kernel<<<Bz * CH, NT, SMEM_SZ>>>(Q, K, V, sf, O);
}

// round 16
// speedup vs baseline: 1.1082x; 1.0960x over previous
#include <cuda_runtime.h>
#include <stdint.h>
#include <math.h>

// =============================== constants ===============================
namespace {
constexpr int Bz = 8, S = 2048, Dh = 128;
constexpr int CH = 16, CR = S / CH;       // 16 split-K chunks of 128 rows
constexpr int PA = 272;                   // A-image pitch (128 bf16 cols)
constexpr int TA = 128 * PA;              // 34816 B
constexpr int PB = 144;                   // B-image pitch (64 bf16 cols)
constexpr int TB = 128 * PB;              // 18432 B
constexpr int SM_AH = 0, SM_AL = TA, SM_BH = 2 * TA, SM_BL = 2 * TA + TB;
constexpr int SMEM_SZ = 2 * TA + 2 * TB;  // 106496 B -> 2 CTAs/SM
constexpr int NT = 256;                   // 8 warps
}

// =============================== scratch =================================
__device__ float    g_Mp[Bz * CH * 128 * 128];  // split-K fp32 partials (8 MB)
__device__ uint32_t g_Mh[Bz][8192];             // M hi, bf16x2 row-major [d][v]
__device__ uint32_t g_Ml[Bz][8192];             // M lo

// =============================== helpers =================================
__device__ __forceinline__ uint32_t smem_u32(const void* p) {
    uint32_t a;
    asm("{ .reg .u64 t; cvta.to.shared.u64 t, %1; cvt.u32.u64 %0, t; }"
        : "=r"(a) : "l"(p));
    return a;
}
__device__ __forceinline__ void cp16(uint32_t dst, const void* src) {
    asm volatile("cp.async.cg.shared.global [%0], [%1], 16;"
                 :: "r"(dst), "l"(src));
}
__device__ __forceinline__ void cp_commit() {
    asm volatile("cp.async.commit_group;");
}
template <int N>
__device__ __forceinline__ void cp_wait() {
    asm volatile("cp.async.wait_group %0;" :: "n"(N));
}
// pack: low half = lo operand, high half = hi operand
__device__ __forceinline__ uint32_t cvt2(float hi, float lo) {
    uint32_t r;
    asm("cvt.rn.bf16x2.f32 %0, %1, %2;" : "=r"(r) : "f"(hi), "f"(lo));
    return r;
}
__device__ __forceinline__ void ldsm4(uint32_t* r, uint32_t a) {
    asm volatile("ldmatrix.sync.aligned.m8n8.x4.shared.b16 {%0,%1,%2,%3}, [%4];"
        : "=r"(r[0]), "=r"(r[1]), "=r"(r[2]), "=r"(r[3]) : "r"(a));
}
__device__ __forceinline__ void ldsm4t(uint32_t* r, uint32_t a) {
    asm volatile("ldmatrix.sync.aligned.m8n8.x4.trans.shared.b16 {%0,%1,%2,%3}, [%4];"
        : "=r"(r[0]), "=r"(r[1]), "=r"(r[2]), "=r"(r[3]) : "r"(a));
}
__device__ __forceinline__ void mma_bf16(float* d, const uint32_t* a,
                                         const uint32_t* b) {
    asm volatile(
        "mma.sync.aligned.m16n8k16.row.col.f32.bf16.bf16.f32 "
        "{%0,%1,%2,%3}, {%4,%5,%6,%7}, {%8,%9}, {%0,%1,%2,%3};"
        : "+f"(d[0]), "+f"(d[1]), "+f"(d[2]), "+f"(d[3])
        : "r"(a[0]), "r"(a[1]), "r"(a[2]), "r"(a[3]), "r"(b[0]), "r"(b[1]));
}

// convert one float4 -> hi/lo bf16x2 pairs, store at (row, col4), pitch P
template <int P>
__device__ __forceinline__ void cvt_store(float4 x, char* hi, char* lo,
                                          int row, int c4) {
    uint32_t h0 = cvt2(x.y, x.x), h1 = cvt2(x.w, x.z);
    float a0 = __uint_as_float(h0 << 16);
    float a1 = __uint_as_float(h0 & 0xFFFF0000u);
    float a2 = __uint_as_float(h1 << 16);
    float a3 = __uint_as_float(h1 & 0xFFFF0000u);
    uint32_t l0 = cvt2(x.y - a1, x.x - a0);
    uint32_t l1 = cvt2(x.w - a3, x.z - a2);
    *(uint2*)(hi + row * P + c4 * 2) = make_uint2(h0, h1);
    *(uint2*)(lo + row * P + c4 * 2) = make_uint2(l0, l1);
}

// one k16 MMA step; warp tile 32x32 over a 128x64 CTA tile (8 warps).
// A images pitch PA (128 cols), B images pitch PB (64 cols).
template <bool ATRANS>
__device__ __forceinline__ void mma_step(uint32_t aA, uint32_t bA, int ks,
                                         float acc[2][4][4]) {
    uint32_t ah[2][4], al[2][4];
    if (ATRANS) {
        const uint32_t kb = (uint32_t)(ks * 16 * PA);
        ldsm4t(ah[0], aA + kb);
        ldsm4t(ah[1], aA + kb + 32);
        ldsm4t(al[0], aA + kb + TA);
        ldsm4t(al[1], aA + kb + TA + 32);
    } else {
        const uint32_t kb = (uint32_t)(ks * 32);
        ldsm4(ah[0], aA + kb);
        ldsm4(ah[1], aA + kb + 16 * PA);
        ldsm4(al[0], aA + kb + TA);
        ldsm4(al[1], aA + kb + TA + 16 * PA);
    }
    const uint32_t kbB = (uint32_t)(ks * 16 * PB);
    uint32_t bh[8], bl[8];
    ldsm4t(&bh[0], bA + kbB);
    ldsm4t(&bh[4], bA + kbB + 32);
    ldsm4t(&bl[0], bA + kbB + TB);
    ldsm4t(&bl[4], bA + kbB + TB + 32);
#pragma unroll
    for (int mt = 0; mt < 2; ++mt)
#pragma unroll
        for (int j = 0; j < 4; ++j) {
            float* d = acc[mt][j];
            mma_bf16(d, ah[mt], &bh[2 * j]);
            mma_bf16(d, al[mt], &bh[2 * j]);
            mma_bf16(d, ah[mt], &bl[2 * j]);
        }
}

// fragment base addresses: 8 warps, warp tile 32x32 (m: wid&3, n: wid>>2)
template <bool ATRANS>
__device__ __forceinline__ void frag_bases(uint32_t sb, int lane, int wid,
                                           uint32_t& aA, uint32_t& bA) {
    const int m_base = (wid & 3) * 32, n_base = (wid >> 2) * 32;
    if (ATRANS) {
        aA = sb + (uint32_t)((((lane & 7) + ((lane >> 4) << 3)) * PA) +
                             (m_base + ((lane >> 3) & 1) * 8) * 2);
    } else {
        aA = sb + (uint32_t)(((m_base + (lane & 7) + (((lane >> 3) & 1) << 3)) *
                              PA) + ((lane >> 4) << 3) * 2);
    }
    bA = sb + SM_BH +
         (uint32_t)((((lane & 7) + (((lane >> 3) & 1) << 3)) * PB) +
                    (n_base + ((lane >> 4) << 3)) * 2);
}

// ==== kernel 1: split-K partial of M = K^T V; CTA = 128 d x 64 v half ====
__global__ void __launch_bounds__(NT, 2)
ktv_kernel(const float* __restrict__ Kp, const float* __restrict__ Vp) {
    extern __shared__ char sm[];
    const uint32_t sb = smem_u32(sm);
    const int tid = threadIdx.x, lane = tid & 31, wid = tid >> 5;
    const int b = blockIdx.x >> 5, c = (blockIdx.x >> 1) & 15;
    const int h = blockIdx.x & 1;          // v-half

    const float4* Kb = (const float4*)(Kp + (size_t)(b * S + c * CR) * Dh);
    const float4* Vb = (const float4*)(Vp + (size_t)(b * S + c * CR) * Dh +
                                       h * 64);

    // load + convert in 2 sub-batches of 64 s-rows (MLP 12 f4/thread)
#pragma unroll
    for (int sub = 0; sub < 2; ++sub) {
        float4 kf[8], vf[4];
#pragma unroll
        for (int t = 0; t < 8; ++t) {
            const int i = t * NT + tid;
            kf[t] = Kb[(sub * 64 + (i >> 5)) * 32 + (i & 31)];
        }
#pragma unroll
        for (int t = 0; t < 4; ++t) {
            const int i = t * NT + tid;
            vf[t] = Vb[(sub * 64 + (i >> 4)) * 32 + (i & 15)];
        }
#pragma unroll
        for (int t = 0; t < 8; ++t) {
            const int i = t * NT + tid;
            cvt_store<PA>(kf[t], sm + SM_AH, sm + SM_AL,
                          sub * 64 + (i >> 5), (i & 31) * 4);
        }
#pragma unroll
        for (int t = 0; t < 4; ++t) {
            const int i = t * NT + tid;
            cvt_store<PB>(vf[t], sm + SM_BH, sm + SM_BL,
                          sub * 64 + (i >> 4), (i & 15) * 4);
        }
    }
    __syncthreads();

    uint32_t aA, bA;
    frag_bases<true>(sb, lane, wid, aA, bA);
    float acc[2][4][4] = {};
#pragma unroll
    for (int s = 0; s < 8; ++s) mma_step<true>(aA, bA, s, acc);

    const int m_base = (wid & 3) * 32, n_base = (wid >> 2) * 32;
    const int g = lane >> 2, t = lane & 3;
    float* outp = g_Mp + ((size_t)(b * CH + c)) * 16384;
#pragma unroll
    for (int mt = 0; mt < 2; ++mt)
#pragma unroll
        for (int nt = 0; nt < 4; ++nt) {
            const int row = m_base + mt * 16 + g;
            const int col = h * 64 + n_base + nt * 8 + 2 * t;
            *(float2*)&outp[row * 128 + col] =
                make_float2(acc[mt][nt][0], acc[mt][nt][1]);
            *(float2*)&outp[(row + 8) * 128 + col] =
                make_float2(acc[mt][nt][2], acc[mt][nt][3]);
        }
}

// ====== kernel 2: reduce 16 partials -> M, convert to bf16 hi/lo ======
__global__ void __launch_bounds__(256, 1) reduce_kernel() {
    const int b = blockIdx.x >> 4, seg = blockIdx.x & 15;
    const int tid = threadIdx.x;
    const int d = seg * 8 + (tid >> 5), v0 = (tid & 31) * 4;
    const float* base = g_Mp + (size_t)b * CH * 16384 + d * 128 + v0;
    float4 s = make_float4(0.f, 0.f, 0.f, 0.f);
#pragma unroll
    for (int c = 0; c < CH; ++c) {
        float4 p = *(const float4*)(base + (size_t)c * 16384);
        s.x += p.x; s.y += p.y; s.z += p.z; s.w += p.w;
    }
    uint32_t h0 = cvt2(s.y, s.x), h1 = cvt2(s.w, s.z);
    float a0 = __uint_as_float(h0 << 16), a1 = __uint_as_float(h0 & 0xFFFF0000u);
    float a2 = __uint_as_float(h1 << 16), a3 = __uint_as_float(h1 & 0xFFFF0000u);
    uint32_t l0 = cvt2(s.y - a1, s.x - a0), l1 = cvt2(s.w - a3, s.z - a2);
    const int w = d * 64 + v0 / 2;
    *(uint2*)&g_Mh[b][w] = make_uint2(h0, h1);
    *(uint2*)&g_Ml[b][w] = make_uint2(l0, l1);
}

// ==== kernel 3: O = Q @ M (scaled); CTA = 128 q-rows x 64 O-col half ====
__global__ void __launch_bounds__(NT, 2)
qm_kernel(const float* __restrict__ Qp, const float* __restrict__ sfp,
          float* __restrict__ Op) {
    extern __shared__ char sm[];
    const uint32_t sb = smem_u32(sm);
    const int tid = threadIdx.x, lane = tid & 31, wid = tid >> 5;
    const int b = blockIdx.x >> 5, qt = (blockIdx.x >> 1) & 15;
    const int h = blockIdx.x & 1;          // O-col half

    // M hi/lo half-columns -> B images via cp.async (one group)
#pragma unroll
    for (int i = 0; i < 8; ++i) {
        const int idx = i * NT + tid;             // 0..2047
        const int rowchunk = idx & 1023;
        const int row = rowchunk >> 3, chk = rowchunk & 7;
        const char* src =
            ((i < 4) ? (const char*)g_Mh[b] : (const char*)g_Ml[b]) +
            (size_t)row * 256 + h * 128 + chk * 16;
        const uint32_t dst = sb + ((i < 4) ? SM_BH : SM_BL) +
                             row * PB + chk * 16;
        cp16(dst, src);
    }
    cp_commit();

    // Q full tile -> A images (2 sub-batches of 8 f4/thread)
    const float4* Qb = (const float4*)(Qp + (size_t)(b * S + qt * 128) * Dh);
#pragma unroll
    for (int sub = 0; sub < 2; ++sub) {
        float4 qf[8];
#pragma unroll
        for (int t = 0; t < 8; ++t) {
            const int i = t * NT + tid;
            qf[t] = Qb[(sub * 64 + (i >> 5)) * 32 + (i & 31)];
        }
#pragma unroll
        for (int t = 0; t < 8; ++t) {
            const int i = t * NT + tid;
            cvt_store<PA>(qf[t], sm + SM_AH, sm + SM_AL,
                          sub * 64 + (i >> 5), (i & 31) * 4);
        }
    }
    cp_wait<0>();
    __syncthreads();

    uint32_t aA, bA;
    frag_bases<false>(sb, lane, wid, aA, bA);
    float acc[2][4][4] = {};
#pragma unroll
    for (int s = 0; s < 8; ++s) mma_step<false>(aA, bA, s, acc);

    const float inv = 1.0f / (sqrtf(128.0f) * sfp[0]);
    const int m_base = (wid & 3) * 32, n_base = (wid >> 2) * 32;
    const int g = lane >> 2, t = lane & 3;
    float* outp = Op + (size_t)(b * S + qt * 128) * 128;
#pragma unroll
    for (int mt = 0; mt < 2; ++mt)
#pragma unroll
        for (int nt = 0; nt < 4; ++nt) {
            const int row = m_base + mt * 16 + g;
            const int col = h * 64 + n_base + nt * 8 + 2 * t;
            *(float2*)&outp[row * 128 + col] =
                make_float2(acc[mt][nt][0] * inv, acc[mt][nt][1] * inv);
            *(float2*)&outp[(row + 8) * 128 + col] =
                make_float2(acc[mt][nt][2] * inv, acc[mt][nt][3] * inv);
        }
}

// =============================== launch ===============================
extern "C" void kernel_launch(void* const* d_in, const int* in_sizes, int n_in,
                              void* d_out, int out_size) {
    // metadata order: qk (unused), qk_scaling_factor, query, key, value
    const float* sf = (const float*)d_in[1];
    const float* Q  = (const float*)d_in[2];
    const float* K  = (const float*)d_in[3];
    const float* V  = (const float*)d_in[4];
    float* O        = (float*)d_out;

    cudaFuncSetAttribute(ktv_kernel,
                         cudaFuncAttributeMaxDynamicSharedMemorySize, SMEM_SZ);
    cudaFuncSetAttribute(qm_kernel,
                         cudaFuncAttributeMaxDynamicSharedMemorySize, SMEM_SZ);

    ktv_kernel<<<Bz * CH * 2, NT, SMEM_SZ>>>(K, V);
    reduce_kernel<<<Bz * CH, 256>>>();
    qm_kernel<<<Bz * CH * 2, NT, SMEM_SZ>>>(Q, sf, O);
}